// round 15
// baseline (speedup 1.0000x reference)
#include <cuda_runtime.h>
#include <cuda_fp16.h>
#include <cstdint>
#include <math.h>

#define BB 4
#define SS 2048
#define DD 2048
#define MM (BB*SS)   /* 8192 */

// ---------------- scratch (allocation-free: __device__ globals) ----------------
__device__ __half g_xh[(size_t)MM*DD];    // fp16 x
__device__ __half g_cxs[(size_t)MM*DD];   // fp16 cumsum(x)/(s+1); reused for fp16 res
__device__ __half g_hh[(size_t)MM*DD];    // fp16 hidden
__device__ __half g_Wth[(size_t)6144*DD]; // fp16 transposed weights [N][K]: ff1 (4096K) | ff2
__device__ __half g_Wvh[(size_t)DD*DD];   // fp16 W_val (original [i][o] layout)
__device__ __half g_Woph[(size_t)DD*DD];  // fp16 W_op (original [o][n] layout)
__device__ __half g_Wct[(size_t)DD*DD];   // fp16 Wcomb^T = (W_op @ ff1_op)^T  [n][o]
__device__ __half g_Wbt[(size_t)DD*DD];   // fp16 Wbig^T  = (W_val @ Wcomb)^T  [n][i]
__device__ float  g_vb[BB*DD];            // vector @ ff1_op + ff1_b
__device__ float  g_vbp[16*BB*DD];        // vb split-j partials
__device__ float  g_csum[BB*8*DD];

#define FF1_T  0
#define FF2_T  ((size_t)2*DD*DD)

// ---------------- helpers ----------------
__device__ __forceinline__ void mma16(float (&c)[4], const uint32_t (&a)[4],
                                      uint32_t b0, uint32_t b1){
    asm volatile("mma.sync.aligned.m16n8k16.row.col.f32.f16.f16.f32 "
        "{%0,%1,%2,%3}, {%4,%5,%6,%7}, {%8,%9}, {%0,%1,%2,%3};\n"
        : "+f"(c[0]), "+f"(c[1]), "+f"(c[2]), "+f"(c[3])
        : "r"(a[0]), "r"(a[1]), "r"(a[2]), "r"(a[3]), "r"(b0), "r"(b1));
}

__device__ __forceinline__ void ldsm4(uint32_t (&d)[4], uint32_t saddr){
    asm volatile("ldmatrix.sync.aligned.m8n8.x4.shared.b16 {%0,%1,%2,%3}, [%4];"
        : "=r"(d[0]), "=r"(d[1]), "=r"(d[2]), "=r"(d[3]) : "r"(saddr));
}

__device__ __forceinline__ void cp16(uint32_t saddr, const void* gptr){
    asm volatile("cp.async.cg.shared.global [%0], [%1], 16;\n" :: "r"(saddr), "l"(gptr));
}
__device__ __forceinline__ void cp_commit(){ asm volatile("cp.async.commit_group;\n"); }
__device__ __forceinline__ void cp_wait1(){ asm volatile("cp.async.wait_group 1;\n"); }

#define STAGES 3
#define STAGE_BYTES 32768   /* As 128x64 fp16 (16KB) + Bs 128x64 fp16 (16KB) */

// ======== CHAMPION GEMM: 128x128 tile, 256 threads, BK=64, 3 stages, 2 CTA/SM ========
template<bool SPLITK,bool ADDBIAS,bool ADDVEC,bool RELU,bool ADDRESID,bool OUTHALF>
__global__ __launch_bounds__(256,2)
void k_gemm(const __half* __restrict__ A, const __half* __restrict__ A2,
            const __half* __restrict__ Bt, const __half* __restrict__ Bt2,
            void* __restrict__ Cv,
            const float* __restrict__ bias, const float* __restrict__ vec,
            const float* __restrict__ resid, int Ktot, int lda, int ldb)
{
    extern __shared__ __align__(16) char sm[];   // STAGES * 32KB
    const uint32_t smb = (uint32_t)__cvta_generic_to_shared(sm);

    const int tid  = threadIdx.x;
    const int bM   = blockIdx.y << 7;
    const int bN   = blockIdx.x << 7;
    const int lane = tid & 31, warp = tid >> 5;
    const int wm   = (warp & 3) << 5;
    const int wn   = (warp >> 2) << 6;
    const int gid  = lane >> 2, tig = lane & 3;

    const int lr = lane & 7;
    const int qh = (lane >> 3) & 1;
    const int cs = lane >> 4;
    uint32_t aOff[2], bOff[4];
    #pragma unroll
    for(int mt=0; mt<2; mt++) aOff[mt] = (uint32_t)((wm + mt*16 + qh*8 + lr) * 128);
    #pragma unroll
    for(int p=0; p<4; p++)    bOff[p]  = (uint32_t)((wn + p*16 + qh*8 + lr) * 128);

    const int rL[4] = { (tid+0)>>3, (tid+256)>>3, (tid+512)>>3, (tid+768)>>3 };
    const int cL    = tid & 7;

    float acc[2][8][4];
    #pragma unroll
    for(int i=0;i<2;i++)
        #pragma unroll
        for(int j=0;j<8;j++)
            #pragma unroll
            for(int k=0;k<4;k++) acc[i][j][k]=0.f;

    const int ntiles = Ktot >> 6;

    auto load_stage = [&](int kt, int slot){
        const int kbase = kt << 6;
        const __half* srcA = A; const __half* srcB = Bt;
        int koff = kbase; int sA = lda, sB = ldb;
        if (SPLITK && kbase >= DD){
            srcA = A2; srcB = Bt2; koff = kbase - DD; sA = DD; sB = DD;
        }
        const uint32_t aBase = smb + slot*STAGE_BYTES;
        const uint32_t bBase = aBase + 16384;
        #pragma unroll
        for(int i=0;i<4;i++){
            int r = rL[i];
            uint32_t soff = (uint32_t)((r*8 + (cL ^ (r&7)))<<4);
            cp16(aBase + soff, srcA + (size_t)(bM+r)*sA + koff + (cL<<3));
            cp16(bBase + soff, srcB + (size_t)(bN+r)*sB + koff + (cL<<3));
        }
    };

    load_stage(0, 0); cp_commit();
    load_stage(1, 1); cp_commit();

    for(int kt=0; kt<ntiles; kt++){
        cp_wait1();
        __syncthreads();

        const uint32_t aBase = smb + (kt%STAGES)*STAGE_BYTES;
        const uint32_t bBase = aBase + 16384;

        #pragma unroll
        for(int ki=0; ki<4; ki++){
            const uint32_t xoff = (uint32_t)((((ki<<1) + cs) ^ lr) << 4);
            uint32_t afr[2][4];
            ldsm4(afr[0], aBase + aOff[0] + xoff);
            ldsm4(afr[1], aBase + aOff[1] + xoff);
            uint32_t bf[4][4];
            #pragma unroll
            for(int p=0;p<4;p++) ldsm4(bf[p], bBase + bOff[p] + xoff);

            #pragma unroll
            for(int mt=0;mt<2;mt++)
                #pragma unroll
                for(int nt=0;nt<8;nt++)
                    mma16(acc[mt][nt], afr[mt], bf[nt>>1][nt&1], bf[nt>>1][2+(nt&1)]);
        }

        int nk = kt + STAGES - 1;
        if (nk < ntiles) load_stage(nk, nk%STAGES);
        cp_commit();
    }

    #pragma unroll
    for(int mt=0;mt<2;mt++){
        #pragma unroll
        for(int nt=0;nt<8;nt++){
            int col = bN + wn + (nt<<3) + (tig<<1);
            #pragma unroll
            for(int rr=0;rr<2;rr++){
                int row = bM + wm + (mt<<4) + gid + (rr<<3);
                float v0 = acc[mt][nt][rr*2+0];
                float v1 = acc[mt][nt][rr*2+1];
                if (ADDBIAS){ v0 += bias[col]; v1 += bias[col+1]; }
                if (ADDVEC){ int b0 = row>>11; v0 += vec[b0*DD+col]; v1 += vec[b0*DD+col+1]; }
                if (RELU){ v0 = fmaxf(v0,0.f); v1 = fmaxf(v1,0.f); }
                if (ADDRESID){
                    v0 += resid[(size_t)row*DD+col];
                    v1 += resid[(size_t)row*DD+col+1];
                }
                if (OUTHALF){
                    __half2 hv = __floats2half2_rn(v0, v1);
                    *(__half2*)((__half*)Cv + (size_t)row*DD + col) = hv;
                } else {
                    *(float2*)((float*)Cv + (size_t)row*DD + col) = make_float2(v0,v1);
                }
            }
        }
    }
}

// ---- shared GEMM core for weight GEMMs (callable from heterogeneous kernels) ----
__device__ void gemm_core_s(int bM, int bN,
                            const __half* __restrict__ A, const __half* __restrict__ Bt,
                            __half* __restrict__ C, int Ktot, int lda, int ldb,
                            char* sm)
{
    const uint32_t smb = (uint32_t)__cvta_generic_to_shared(sm);
    const int tid  = threadIdx.x;
    const int lane = tid & 31, warp = tid >> 5;
    const int wm   = (warp & 3) << 5;
    const int wn   = (warp >> 2) << 6;
    const int gid  = lane >> 2, tig = lane & 3;

    const int lr = lane & 7;
    const int qh = (lane >> 3) & 1;
    const int cs = lane >> 4;
    uint32_t aOff[2], bOff[4];
    #pragma unroll
    for(int mt=0; mt<2; mt++) aOff[mt] = (uint32_t)((wm + mt*16 + qh*8 + lr) * 128);
    #pragma unroll
    for(int p=0; p<4; p++)    bOff[p]  = (uint32_t)((wn + p*16 + qh*8 + lr) * 128);

    const int rL[4] = { (tid+0)>>3, (tid+256)>>3, (tid+512)>>3, (tid+768)>>3 };
    const int cL    = tid & 7;

    float acc[2][8][4];
    #pragma unroll
    for(int i=0;i<2;i++)
        #pragma unroll
        for(int j=0;j<8;j++)
            #pragma unroll
            for(int k=0;k<4;k++) acc[i][j][k]=0.f;

    const int ntiles = Ktot >> 6;

    auto load_stage = [&](int kt, int slot){
        const int kbase = kt << 6;
        const uint32_t aBase = smb + slot*STAGE_BYTES;
        const uint32_t bBase = aBase + 16384;
        #pragma unroll
        for(int i=0;i<4;i++){
            int r = rL[i];
            uint32_t soff = (uint32_t)((r*8 + (cL ^ (r&7)))<<4);
            cp16(aBase + soff, A + (size_t)(bM+r)*lda + kbase + (cL<<3));
            cp16(bBase + soff, Bt + (size_t)(bN+r)*ldb + kbase + (cL<<3));
        }
    };

    load_stage(0, 0); cp_commit();
    load_stage(1, 1); cp_commit();

    for(int kt=0; kt<ntiles; kt++){
        cp_wait1();
        __syncthreads();

        const uint32_t aBase = smb + (kt%STAGES)*STAGE_BYTES;
        const uint32_t bBase = aBase + 16384;

        #pragma unroll
        for(int ki=0; ki<4; ki++){
            const uint32_t xoff = (uint32_t)((((ki<<1) + cs) ^ lr) << 4);
            uint32_t afr[2][4];
            ldsm4(afr[0], aBase + aOff[0] + xoff);
            ldsm4(afr[1], aBase + aOff[1] + xoff);
            uint32_t bf[4][4];
            #pragma unroll
            for(int p=0;p<4;p++) ldsm4(bf[p], bBase + bOff[p] + xoff);

            #pragma unroll
            for(int mt=0;mt<2;mt++)
                #pragma unroll
                for(int nt=0;nt<8;nt++)
                    mma16(acc[mt][nt], afr[mt], bf[nt>>1][nt&1], bf[nt>>1][2+(nt&1)]);
        }

        int nk = kt + STAGES - 1;
        if (nk < ntiles) load_stage(nk, nk%STAGES);
        cp_commit();
    }

    #pragma unroll
    for(int mt=0;mt<2;mt++){
        #pragma unroll
        for(int nt=0;nt<8;nt++){
            int col = bN + wn + (nt<<3) + (tig<<1);
            #pragma unroll
            for(int rr=0;rr<2;rr++){
                int row = bM + wm + (mt<<4) + gid + (rr<<3);
                __half2 hv = __floats2half2_rn(acc[mt][nt][rr*2+0], acc[mt][nt][rr*2+1]);
                *(__half2*)(C + (size_t)row*DD + col) = hv;
            }
        }
    }
}

// ================= k_prep1: all independent prep in ONE full-machine launch ==========
// ranges: [0,8192)      trh(ff1)   (128 k-tiles x 64 n-tiles)
//         [8192,12288)  trh(ff2)   (64 x 64)
//         [12288,20480) x->fp16
//         [20480,28672) W_op/W_val->fp16
//         [28672,28800) vbp (4-batch fused)
__global__ __launch_bounds__(256)
void k_prep1(const float* __restrict__ ff1, const float* __restrict__ ff2,
             const float* __restrict__ x, const float* __restrict__ W_op,
             const float* __restrict__ W_val, const float* __restrict__ vector,
             __half* __restrict__ Wth, __half* __restrict__ xh,
             __half* __restrict__ Woph, __half* __restrict__ Wvh,
             float* __restrict__ vbp)
{
    __shared__ float t[32][33];
    const int id = blockIdx.x;
    const int tid = threadIdx.x;

    if (id < 12288){
        // transpose + fp16: Wt[n][k] = h(W[k][n]); unit = (kb-tile, nb-tile)
        const float* W; __half* Wt; int K, N, u;
        if (id < 8192){ W = ff1; Wt = Wth + FF1_T; K = 2*DD; N = DD; u = id; }
        else          { W = ff2; Wt = Wth + FF2_T; K = DD;   N = DD; u = id - 8192; }
        const int nb = (u & 63) * 32, kb = (u >> 6) * 32;
        const int tx = tid & 31, ty = tid >> 5;
        #pragma unroll
        for(int i=0;i<32;i+=8) t[ty+i][tx] = W[(size_t)(kb+ty+i)*N + nb+tx];
        __syncthreads();
        #pragma unroll
        for(int i=0;i<32;i+=8)
            Wt[(size_t)(nb+ty+i)*K + kb+tx] = __float2half(t[tx][ty+i]);
    } else if (id < 20480){
        // x -> fp16, 2 float4 per thread
        const int blk = id - 12288;
        const int base = blk*512 + tid;
        #pragma unroll
        for(int rep=0; rep<2; rep++){
            int i = base + rep*256;
            float4 a = ((const float4*)x)[i];
            __half2 h0 = __floats2half2_rn(a.x, a.y);
            __half2 h1 = __floats2half2_rn(a.z, a.w);
            ((uint2*)xh)[i] = make_uint2(*(uint32_t*)&h0, *(uint32_t*)&h1);
        }
    } else if (id < 28672){
        const int j = id - 20480;
        const float* src = (j < 4096) ? W_op : W_val;
        __half* dst = (j < 4096) ? Woph : Wvh;
        const int i = (j & 4095)*256 + tid;
        float4 a = ((const float4*)src)[i];
        __half2 h0 = __floats2half2_rn(a.x, a.y);
        __half2 h1 = __floats2half2_rn(a.z, a.w);
        ((uint2*)dst)[i] = make_uint2(*(uint32_t*)&h0, *(uint32_t*)&h1);
    } else {
        // vbp, 4 batches fused: unit u = (strip, z)
        const int u = id - 28672;          // [0,128)
        const int strip = u & 7, z = u >> 3;
        const int col = strip*256 + tid;
        const int j0 = z << 7;
        float a0=0.f, a1=0.f, a2=0.f, a3=0.f;
        #pragma unroll 8
        for(int j=j0; j<j0+128; j++){
            float w = ff1[(size_t)(DD+j)*DD + col];
            a0 += __ldg(vector + 0*DD + j) * w;
            a1 += __ldg(vector + 1*DD + j) * w;
            a2 += __ldg(vector + 2*DD + j) * w;
            a3 += __ldg(vector + 3*DD + j) * w;
        }
        vbp[((size_t)(z*BB+0))*DD + col] = a0;
        vbp[((size_t)(z*BB+1))*DD + col] = a1;
        vbp[((size_t)(z*BB+2))*DD + col] = a2;
        vbp[((size_t)(z*BB+3))*DD + col] = a3;
    }
}

// ================= k_wg1: Wcomb GEMM (256 blocks) + chunksum aux (40 blocks) =========
__global__ __launch_bounds__(256,2)
void k_wg1(const __half* __restrict__ ff1t_op, const __half* __restrict__ Woph,
           __half* __restrict__ Wct,
           const __half* __restrict__ xh, float* __restrict__ csum)
{
    extern __shared__ __align__(16) char sm[];
    const int id = blockIdx.x;
    if (id < 256){
        gemm_core_s((id>>4)<<7, (id&15)<<7, ff1t_op, Woph, Wct, DD, 2*DD, DD, sm);
        return;
    }
    // chunksum aux: units u = (id-256) + 40*t
    const int tid = threadIdx.x;
    for(int u = id-256; u < 256; u += 40){
        int col   = ((u & 7)<<8) + tid;
        int chunk = (u>>3) & 7;
        int b     = u>>6;
        const __half* p = xh + ((size_t)(b*SS + (chunk<<8)))*DD + col;
        float s=0.f;
        #pragma unroll 16
        for(int i=0;i<256;i++) s += __half2float(p[(size_t)i*DD]);
        csum[((size_t)(b*8+chunk))*DD + col] = s;
    }
}

// ================= k_wg2: Wbig GEMM (256) + scan aux (36) + vbr aux (4) ==============
__global__ __launch_bounds__(256,2)
void k_wg2(const __half* __restrict__ Wct, const __half* __restrict__ Wvh,
           __half* __restrict__ Wbt,
           const __half* __restrict__ xh, const float* __restrict__ csum,
           __half* __restrict__ cxs,
           const float* __restrict__ vbp, const float* __restrict__ ff1_b,
           float* __restrict__ vb)
{
    extern __shared__ __align__(16) char sm[];
    const int id = blockIdx.x;
    const int tid = threadIdx.x;
    if (id < 256){
        gemm_core_s((id>>4)<<7, (id&15)<<7, Wct, Wvh, Wbt, DD, DD, DD, sm);
        return;
    }
    if (id < 292){
        // scan aux: units u = (id-256) + 36*t
        for(int u = id-256; u < 256; u += 36){
            int col   = ((u & 7)<<8) + tid;
            int chunk = (u>>3) & 7;
            int b     = u>>6;
            float run = 0.f;
            for(int c=0;c<chunk;c++) run += csum[((size_t)(b*8+c))*DD + col];
            const __half* p = xh + ((size_t)(b*SS + (chunk<<8)))*DD + col;
            __half* q = cxs + ((size_t)(b*SS + (chunk<<8)))*DD + col;
            const int s0 = chunk<<8;
            #pragma unroll 8
            for(int i=0;i<256;i++){
                run += __half2float(p[(size_t)i*DD]);
                q[(size_t)i*DD] = __float2half(run * __frcp_rn((float)(s0+i+1)));
            }
        }
        return;
    }
    // vbr aux: units u = (id-292) + 4*t over 32
    for(int u = id-292; u < 32; u += 4){
        int strip = u & 7, b = u >> 3;
        int col = strip*256 + tid;
        float a = ff1_b[col];
        #pragma unroll
        for(int z=0;z<16;z++) a += vbp[((size_t)(z*BB+b))*DD + col];
        vb[b*DD + col] = a;
    }
}

// ---------------- row LayerNorm (fp16 res input) ----------------
__global__ void k_ln(const __half* __restrict__ res, const float* __restrict__ gamma,
                     const float* __restrict__ beta, float* __restrict__ out){
    const int row = blockIdx.x;
    const __half* r = res + (size_t)row*DD;
    __shared__ float srow[DD];
    __shared__ float red[8];
    int lane = threadIdx.x & 31, warp = threadIdx.x >> 5;

    float s=0.f;
    for(int d=threadIdx.x; d<DD; d+=256){ float v=__half2float(r[d]); srow[d]=v; s+=v; }
    #pragma unroll
    for(int o=16;o>0;o>>=1) s += __shfl_xor_sync(0xffffffffu, s, o);
    if(lane==0) red[warp]=s;
    __syncthreads();
    float mean = (red[0]+red[1]+red[2]+red[3]+red[4]+red[5]+red[6]+red[7]) * (1.f/DD);

    float v2=0.f;
    for(int d=threadIdx.x; d<DD; d+=256){ float c=srow[d]-mean; v2+=c*c; }
    #pragma unroll
    for(int o=16;o>0;o>>=1) v2 += __shfl_xor_sync(0xffffffffu, v2, o);
    __syncthreads();
    if(lane==0) red[warp]=v2;
    __syncthreads();
    float var  = (red[0]+red[1]+red[2]+red[3]+red[4]+red[5]+red[6]+red[7]) * (1.f/DD);
    float rstd = rsqrtf(var + 1e-6f);

    for(int d=threadIdx.x; d<DD; d+=256)
        out[(size_t)row*DD + d] = (srow[d]-mean)*rstd*gamma[d] + beta[d];
}

// ---------------- launch ----------------
extern "C" void kernel_launch(void* const* d_in, const int* in_sizes, int n_in,
                              void* d_out, int out_size)
{
    const float* x      = (const float*)d_in[0];
    const float* vector = (const float*)d_in[1];
    const float* W_val  = (const float*)d_in[4];
    const float* W_op   = (const float*)d_in[5];
    const float* ff1    = (const float*)d_in[6];
    const float* ff1_b  = (const float*)d_in[7];
    const float* ff2    = (const float*)d_in[8];
    const float* ff2_b  = (const float*)d_in[9];
    const float* gamma  = (const float*)d_in[10];
    const float* beta   = (const float*)d_in[11];
    float* out = (float*)d_out;
    (void)in_sizes; (void)n_in; (void)out_size;

    float *csum,*vb,*vbp;
    __half *xh,*cxs,*hh,*Wth,*Wvh,*Woph,*Wct,*Wbt;
    cudaGetSymbolAddress((void**)&xh, g_xh);
    cudaGetSymbolAddress((void**)&cxs, g_cxs);
    cudaGetSymbolAddress((void**)&hh, g_hh);
    cudaGetSymbolAddress((void**)&Wth, g_Wth);
    cudaGetSymbolAddress((void**)&Wvh, g_Wvh);
    cudaGetSymbolAddress((void**)&Woph, g_Woph);
    cudaGetSymbolAddress((void**)&Wct, g_Wct);
    cudaGetSymbolAddress((void**)&Wbt, g_Wbt);
    cudaGetSymbolAddress((void**)&vb, g_vb);
    cudaGetSymbolAddress((void**)&vbp, g_vbp);
    cudaGetSymbolAddress((void**)&csum, g_csum);

    const int gemm_smem = STAGES * STAGE_BYTES;   // 96KB
    cudaFuncSetAttribute(k_gemm<true,false,true,true,false,true>,
                         cudaFuncAttributeMaxDynamicSharedMemorySize, gemm_smem);
    cudaFuncSetAttribute(k_gemm<false,true,false,true,true,true>,
                         cudaFuncAttributeMaxDynamicSharedMemorySize, gemm_smem);
    cudaFuncSetAttribute(k_wg1, cudaFuncAttributeMaxDynamicSharedMemorySize, gemm_smem);
    cudaFuncSetAttribute(k_wg2, cudaFuncAttributeMaxDynamicSharedMemorySize, gemm_smem);

    // 1) all independent prep in one launch
    k_prep1<<<28800, 256>>>(ff1, ff2, x, W_op, W_val, vector,
                            Wth, xh, Woph, Wvh, vbp);

    // 2) Wcomb_t[n][o] = sum_j ff1_op[j][n] * W_op[o][j]  (+ chunksum aux)
    k_wg1<<<296, 256, gemm_smem>>>(Wth + FF1_T + DD, Woph, Wct, xh, csum);

    // 3) Wbig_t[n][i] = sum_o Wcomb_t[n][o] * W_val[i][o]  (+ scan & vbr aux)
    k_wg2<<<296, 256, gemm_smem>>>(Wct, Wvh, Wbt, xh, csum, cxs, vbp, ff1_b, vb);

    dim3 gg(DD/128, MM/128);   // (16, 64)

    // 4) h = relu( x@ff1_x + cxs@Wbig + vb )   (fp16 out)
    k_gemm<true,false,true,true,false,true><<<gg,256,gemm_smem>>>(
        xh, cxs, Wth + FF1_T, Wbt, hh,
        nullptr, vb, nullptr, 2*DD, DD, 2*DD);
    // 5) res = relu(h @ ff2 + b) + x   (fp16 out into cxs buffer — cxs dead now)
    k_gemm<false,true,false,true,true,true><<<gg,256,gemm_smem>>>(
        hh, nullptr, Wth + FF2_T, nullptr, cxs,
        ff2_b, nullptr, x, DD, DD, DD);
    // 6) out = layernorm(res)
    k_ln<<<MM, 256>>>(cxs, gamma, beta, out);
}

// round 16
// speedup vs baseline: 1.6860x; 1.6860x over previous
#include <cuda_runtime.h>
#include <cuda_fp16.h>
#include <cstdint>
#include <math.h>

#define BB 4
#define SS 2048
#define DD 2048
#define MM (BB*SS)   /* 8192 */

// ---------------- scratch (allocation-free: __device__ globals) ----------------
__device__ __half g_xh[(size_t)MM*DD];    // fp16 x
__device__ __half g_cxs[(size_t)MM*DD];   // fp16 cumsum(x)/(s+1); reused for fp16 res
__device__ __half g_hh[(size_t)MM*DD];    // fp16 hidden
__device__ __half g_Wth[(size_t)6144*DD]; // fp16 transposed weights [N][K]: ff1 (4096K) | ff2
__device__ __half g_Wvh[(size_t)DD*DD];   // fp16 W_val (original [i][o] layout)
__device__ __half g_Woph[(size_t)DD*DD];  // fp16 W_op (original [o][n] layout)
__device__ __half g_Wct[(size_t)DD*DD];   // fp16 Wcomb^T = (W_op @ ff1_op)^T  [n][o]
__device__ __half g_Wbt[(size_t)DD*DD];   // fp16 Wbig^T  = (W_val @ Wcomb)^T  [n][i]
__device__ float  g_vb[BB*DD];            // vector @ ff1_op + ff1_b
__device__ float  g_vbp[16*BB*DD];        // vb split-j partials
__device__ float  g_csum[BB*8*DD];

#define FF1_T  0
#define FF2_T  ((size_t)2*DD*DD)

// ---------------- helpers ----------------
__device__ __forceinline__ void mma16(float (&c)[4], const uint32_t (&a)[4],
                                      uint32_t b0, uint32_t b1){
    asm volatile("mma.sync.aligned.m16n8k16.row.col.f32.f16.f16.f32 "
        "{%0,%1,%2,%3}, {%4,%5,%6,%7}, {%8,%9}, {%0,%1,%2,%3};\n"
        : "+f"(c[0]), "+f"(c[1]), "+f"(c[2]), "+f"(c[3])
        : "r"(a[0]), "r"(a[1]), "r"(a[2]), "r"(a[3]), "r"(b0), "r"(b1));
}

__device__ __forceinline__ void ldsm4(uint32_t (&d)[4], uint32_t saddr){
    asm volatile("ldmatrix.sync.aligned.m8n8.x4.shared.b16 {%0,%1,%2,%3}, [%4];"
        : "=r"(d[0]), "=r"(d[1]), "=r"(d[2]), "=r"(d[3]) : "r"(saddr));
}

__device__ __forceinline__ void cp16(uint32_t saddr, const void* gptr){
    asm volatile("cp.async.cg.shared.global [%0], [%1], 16;\n" :: "r"(saddr), "l"(gptr));
}
__device__ __forceinline__ void cp_commit(){ asm volatile("cp.async.commit_group;\n"); }
__device__ __forceinline__ void cp_wait1(){ asm volatile("cp.async.wait_group 1;\n"); }

#define STAGES 3
#define STAGE_BYTES 32768   /* As 128x64 fp16 (16KB) + Bs 128x64 fp16 (16KB) */

// ======== CHAMPION GEMM: 128x128 tile, 256 threads, BK=64, 3 stages, 2 CTA/SM ========
// C[M, 2048] = A[M, Ktot] * Bt^T ; A row stride lda, Bt row stride ldb.
// SPLITK: for k>=2048 switches to A2 (stride DD) and Bt2 (stride DD).
// resid is fp16.
template<bool SPLITK,bool ADDBIAS,bool ADDVEC,bool RELU,bool ADDRESID,bool OUTHALF>
__global__ __launch_bounds__(256,2)
void k_gemm(const __half* __restrict__ A, const __half* __restrict__ A2,
            const __half* __restrict__ Bt, const __half* __restrict__ Bt2,
            void* __restrict__ Cv,
            const float* __restrict__ bias, const float* __restrict__ vec,
            const __half* __restrict__ resid, int Ktot, int lda, int ldb)
{
    extern __shared__ __align__(16) char sm[];   // STAGES * 32KB
    const uint32_t smb = (uint32_t)__cvta_generic_to_shared(sm);

    const int tid  = threadIdx.x;
    const int bM   = blockIdx.y << 7;
    const int bN   = blockIdx.x << 7;
    const int lane = tid & 31, warp = tid >> 5;
    const int wm   = (warp & 3) << 5;
    const int wn   = (warp >> 2) << 6;
    const int gid  = lane >> 2, tig = lane & 3;

    const int lr = lane & 7;
    const int qh = (lane >> 3) & 1;
    const int cs = lane >> 4;
    uint32_t aOff[2], bOff[4];
    #pragma unroll
    for(int mt=0; mt<2; mt++) aOff[mt] = (uint32_t)((wm + mt*16 + qh*8 + lr) * 128);
    #pragma unroll
    for(int p=0; p<4; p++)    bOff[p]  = (uint32_t)((wn + p*16 + qh*8 + lr) * 128);

    const int rL[4] = { (tid+0)>>3, (tid+256)>>3, (tid+512)>>3, (tid+768)>>3 };
    const int cL    = tid & 7;

    float acc[2][8][4];
    #pragma unroll
    for(int i=0;i<2;i++)
        #pragma unroll
        for(int j=0;j<8;j++)
            #pragma unroll
            for(int k=0;k<4;k++) acc[i][j][k]=0.f;

    const int ntiles = Ktot >> 6;

    auto load_stage = [&](int kt, int slot){
        const int kbase = kt << 6;
        const __half* srcA = A; const __half* srcB = Bt;
        int koff = kbase; int sA = lda, sB = ldb;
        if (SPLITK && kbase >= DD){
            srcA = A2; srcB = Bt2; koff = kbase - DD; sA = DD; sB = DD;
        }
        const uint32_t aBase = smb + slot*STAGE_BYTES;
        const uint32_t bBase = aBase + 16384;
        #pragma unroll
        for(int i=0;i<4;i++){
            int r = rL[i];
            uint32_t soff = (uint32_t)((r*8 + (cL ^ (r&7)))<<4);
            cp16(aBase + soff, srcA + (size_t)(bM+r)*sA + koff + (cL<<3));
            cp16(bBase + soff, srcB + (size_t)(bN+r)*sB + koff + (cL<<3));
        }
    };

    load_stage(0, 0); cp_commit();
    load_stage(1, 1); cp_commit();

    for(int kt=0; kt<ntiles; kt++){
        cp_wait1();
        __syncthreads();

        const uint32_t aBase = smb + (kt%STAGES)*STAGE_BYTES;
        const uint32_t bBase = aBase + 16384;

        #pragma unroll
        for(int ki=0; ki<4; ki++){
            const uint32_t xoff = (uint32_t)((((ki<<1) + cs) ^ lr) << 4);
            uint32_t afr[2][4];
            ldsm4(afr[0], aBase + aOff[0] + xoff);
            ldsm4(afr[1], aBase + aOff[1] + xoff);
            uint32_t bf[4][4];
            #pragma unroll
            for(int p=0;p<4;p++) ldsm4(bf[p], bBase + bOff[p] + xoff);

            #pragma unroll
            for(int mt=0;mt<2;mt++)
                #pragma unroll
                for(int nt=0;nt<8;nt++)
                    mma16(acc[mt][nt], afr[mt], bf[nt>>1][nt&1], bf[nt>>1][2+(nt&1)]);
        }

        int nk = kt + STAGES - 1;
        if (nk < ntiles) load_stage(nk, nk%STAGES);
        cp_commit();
    }

    // epilogue: thread (gid,tig): rows gid, gid+8; cols 2*tig, 2*tig+1
    #pragma unroll
    for(int mt=0;mt<2;mt++){
        #pragma unroll
        for(int nt=0;nt<8;nt++){
            int col = bN + wn + (nt<<3) + (tig<<1);
            #pragma unroll
            for(int rr=0;rr<2;rr++){
                int row = bM + wm + (mt<<4) + gid + (rr<<3);
                float v0 = acc[mt][nt][rr*2+0];
                float v1 = acc[mt][nt][rr*2+1];
                if (ADDBIAS){ v0 += bias[col]; v1 += bias[col+1]; }
                if (ADDVEC){ int b0 = row>>11; v0 += vec[b0*DD+col]; v1 += vec[b0*DD+col+1]; }
                if (RELU){ v0 = fmaxf(v0,0.f); v1 = fmaxf(v1,0.f); }
                if (ADDRESID){
                    __half2 rh = *(const __half2*)(resid + (size_t)row*DD + col);
                    float2 rf = __half22float2(rh);
                    v0 += rf.x; v1 += rf.y;
                }
                if (OUTHALF){
                    __half2 hv = __floats2half2_rn(v0, v1);
                    *(__half2*)((__half*)Cv + (size_t)row*DD + col) = hv;
                } else {
                    *(float2*)((float*)Cv + (size_t)row*DD + col) = make_float2(v0,v1);
                }
            }
        }
    }
}

// plain weight GEMM (fp16 out), same core, no epilogue extras
__global__ __launch_bounds__(256,2)
void k_gemm_s(const __half* __restrict__ A, const __half* __restrict__ Bt,
              __half* __restrict__ C, int Ktot, int lda, int ldb)
{
    extern __shared__ __align__(16) char sm[];
    const uint32_t smb = (uint32_t)__cvta_generic_to_shared(sm);

    const int tid  = threadIdx.x;
    const int bM   = blockIdx.y << 7;
    const int bN   = blockIdx.x << 7;
    const int lane = tid & 31, warp = tid >> 5;
    const int wm   = (warp & 3) << 5;
    const int wn   = (warp >> 2) << 6;
    const int gid  = lane >> 2, tig = lane & 3;

    const int lr = lane & 7;
    const int qh = (lane >> 3) & 1;
    const int cs = lane >> 4;
    uint32_t aOff[2], bOff[4];
    #pragma unroll
    for(int mt=0; mt<2; mt++) aOff[mt] = (uint32_t)((wm + mt*16 + qh*8 + lr) * 128);
    #pragma unroll
    for(int p=0; p<4; p++)    bOff[p]  = (uint32_t)((wn + p*16 + qh*8 + lr) * 128);

    const int rL[4] = { (tid+0)>>3, (tid+256)>>3, (tid+512)>>3, (tid+768)>>3 };
    const int cL    = tid & 7;

    float acc[2][8][4];
    #pragma unroll
    for(int i=0;i<2;i++)
        #pragma unroll
        for(int j=0;j<8;j++)
            #pragma unroll
            for(int k=0;k<4;k++) acc[i][j][k]=0.f;

    const int ntiles = Ktot >> 6;

    auto load_stage = [&](int kt, int slot){
        const int kbase = kt << 6;
        const uint32_t aBase = smb + slot*STAGE_BYTES;
        const uint32_t bBase = aBase + 16384;
        #pragma unroll
        for(int i=0;i<4;i++){
            int r = rL[i];
            uint32_t soff = (uint32_t)((r*8 + (cL ^ (r&7)))<<4);
            cp16(aBase + soff, A + (size_t)(bM+r)*lda + kbase + (cL<<3));
            cp16(bBase + soff, Bt + (size_t)(bN+r)*ldb + kbase + (cL<<3));
        }
    };

    load_stage(0, 0); cp_commit();
    load_stage(1, 1); cp_commit();

    for(int kt=0; kt<ntiles; kt++){
        cp_wait1();
        __syncthreads();

        const uint32_t aBase = smb + (kt%STAGES)*STAGE_BYTES;
        const uint32_t bBase = aBase + 16384;

        #pragma unroll
        for(int ki=0; ki<4; ki++){
            const uint32_t xoff = (uint32_t)((((ki<<1) + cs) ^ lr) << 4);
            uint32_t afr[2][4];
            ldsm4(afr[0], aBase + aOff[0] + xoff);
            ldsm4(afr[1], aBase + aOff[1] + xoff);
            uint32_t bf[4][4];
            #pragma unroll
            for(int p=0;p<4;p++) ldsm4(bf[p], bBase + bOff[p] + xoff);

            #pragma unroll
            for(int mt=0;mt<2;mt++)
                #pragma unroll
                for(int nt=0;nt<8;nt++)
                    mma16(acc[mt][nt], afr[mt], bf[nt>>1][nt&1], bf[nt>>1][2+(nt&1)]);
        }

        int nk = kt + STAGES - 1;
        if (nk < ntiles) load_stage(nk, nk%STAGES);
        cp_commit();
    }

    #pragma unroll
    for(int mt=0;mt<2;mt++){
        #pragma unroll
        for(int nt=0;nt<8;nt++){
            int col = bN + wn + (nt<<3) + (tig<<1);
            #pragma unroll
            for(int rr=0;rr<2;rr++){
                int row = bM + wm + (mt<<4) + gid + (rr<<3);
                __half2 hv = __floats2half2_rn(acc[mt][nt][rr*2+0], acc[mt][nt][rr*2+1]);
                *(__half2*)(C + (size_t)row*DD + col) = hv;
            }
        }
    }
}

// ---------------- merged weight transpose + fp16: ff1 (y<128) and ff2 (y>=128) --------
__global__ void k_trh2(const float* __restrict__ ff1, const float* __restrict__ ff2,
                       __half* __restrict__ Wth){
    __shared__ float t[32][33];
    const int by = blockIdx.y;
    const float* W; __half* Wt; int K, N, kb;
    if (by < 128){ W = ff1; Wt = Wth + FF1_T; K = 2*DD; N = DD; kb = by*32; }
    else         { W = ff2; Wt = Wth + FF2_T; K = DD;   N = DD; kb = (by-128)*32; }
    const int nb = blockIdx.x*32;
    const int tx = threadIdx.x, ty = threadIdx.y;
    #pragma unroll
    for(int i=0;i<32;i+=8) t[ty+i][tx] = W[(size_t)(kb+ty+i)*N + nb+tx];
    __syncthreads();
    #pragma unroll
    for(int i=0;i<32;i+=8)
        Wt[(size_t)(nb+ty+i)*K + kb+tx] = __float2half(t[tx][ty+i]);
}

// elementwise fp32 -> fp16 (y selects one of two src/dst pairs)
__global__ void k_xh2(const float* __restrict__ s0, __half* __restrict__ d0,
                      const float* __restrict__ s1, __half* __restrict__ d1, int n4){
    int i = blockIdx.x*256 + threadIdx.x;
    const float* src = blockIdx.y ? s1 : s0;
    __half* dst = blockIdx.y ? d1 : d0;
    if (i < n4){
        float4 a = ((const float4*)src)[i];
        __half2 h0 = __floats2half2_rn(a.x, a.y);
        __half2 h1 = __floats2half2_rn(a.z, a.w);
        uint2 u = make_uint2(*(uint32_t*)&h0, *(uint32_t*)&h1);
        ((uint2*)dst)[i] = u;
    }
}
__global__ void k_xh(const float* __restrict__ src, __half* __restrict__ dst, int n4){
    int i = blockIdx.x*256 + threadIdx.x;
    if (i < n4){
        float4 a = ((const float4*)src)[i];
        __half2 h0 = __floats2half2_rn(a.x, a.y);
        __half2 h1 = __floats2half2_rn(a.z, a.w);
        uint2 u = make_uint2(*(uint32_t*)&h0, *(uint32_t*)&h1);
        ((uint2*)dst)[i] = u;
    }
}

// vb split-j partials: part[z][b][col] = sum_{j in z-chunk} vector[b][j]*ff1[2048+j][col]
__global__ void k_vbp(const float* __restrict__ vector, const float* __restrict__ ff1,
                      float* __restrict__ part){
    const int col = blockIdx.x*256 + threadIdx.x;
    const int b   = blockIdx.y, z = blockIdx.z;
    const float* vp = vector + (size_t)b*DD;
    float a = 0.f;
    const int j0 = z << 7;
    #pragma unroll 8
    for(int j=j0; j<j0+128; j++)
        a += __ldg(vp+j) * ff1[(size_t)(DD+j)*DD + col];
    part[((size_t)(z*BB+b))*DD + col] = a;
}
__global__ void k_vbr(const float* __restrict__ part, const float* __restrict__ ff1_b,
                      float* __restrict__ vb){
    const int col = blockIdx.x*256 + threadIdx.x;
    const int b   = blockIdx.y;
    float a = ff1_b[col];
    #pragma unroll
    for(int z=0;z<16;z++) a += part[((size_t)(z*BB+b))*DD + col];
    vb[b*DD + col] = a;
}

// ---------------- causal cumsum of x (two-pass chunked), fp16 in -> fp16 cxs out ----
// reference coef = w/(w*(s+1)+1e-30) == 1/(s+1) to ~1e-27 relative, and cumsum
// commutes with right-multiplication, so pooled@W_op@ff1_op == cxs@Wbig.
__global__ void k_chunksum(const __half* __restrict__ X, float* __restrict__ csum){
    int col   = ((blockIdx.x & 7)<<8) + threadIdx.x;
    int chunk = (blockIdx.x>>3) & 7;
    int b     = blockIdx.x>>6;
    const __half* p = X + ((size_t)(b*SS + (chunk<<8)))*DD + col;
    float s=0.f;
    #pragma unroll 8
    for(int i=0;i<256;i++) s += __half2float(p[(size_t)i*DD]);
    csum[((size_t)(b*8+chunk))*DD + col] = s;
}

__global__ void k_scan(const __half* __restrict__ X, const float* __restrict__ csum,
                       __half* __restrict__ C){
    int col   = ((blockIdx.x & 7)<<8) + threadIdx.x;
    int chunk = (blockIdx.x>>3) & 7;
    int b     = blockIdx.x>>6;
    float run = 0.f;
    for(int c=0;c<chunk;c++) run += csum[((size_t)(b*8+c))*DD + col];
    const __half* p = X + ((size_t)(b*SS + (chunk<<8)))*DD + col;
    __half* q = C + ((size_t)(b*SS + (chunk<<8)))*DD + col;
    const int s0 = chunk<<8;
    #pragma unroll 4
    for(int i=0;i<256;i++){
        run += __half2float(p[(size_t)i*DD]);
        q[(size_t)i*DD] = __float2half(run * __frcp_rn((float)(s0+i+1)));
    }
}

// ---------------- row LayerNorm (fp16 res input) ----------------
__global__ void k_ln(const __half* __restrict__ res, const float* __restrict__ gamma,
                     const float* __restrict__ beta, float* __restrict__ out){
    const int row = blockIdx.x;
    const __half* r = res + (size_t)row*DD;
    __shared__ float srow[DD];
    __shared__ float red[8];
    int lane = threadIdx.x & 31, warp = threadIdx.x >> 5;

    float s=0.f;
    for(int d=threadIdx.x; d<DD; d+=256){ float v=__half2float(r[d]); srow[d]=v; s+=v; }
    #pragma unroll
    for(int o=16;o>0;o>>=1) s += __shfl_xor_sync(0xffffffffu, s, o);
    if(lane==0) red[warp]=s;
    __syncthreads();
    float mean = (red[0]+red[1]+red[2]+red[3]+red[4]+red[5]+red[6]+red[7]) * (1.f/DD);

    float v2=0.f;
    for(int d=threadIdx.x; d<DD; d+=256){ float c=srow[d]-mean; v2+=c*c; }
    #pragma unroll
    for(int o=16;o>0;o>>=1) v2 += __shfl_xor_sync(0xffffffffu, v2, o);
    __syncthreads();
    if(lane==0) red[warp]=v2;
    __syncthreads();
    float var  = (red[0]+red[1]+red[2]+red[3]+red[4]+red[5]+red[6]+red[7]) * (1.f/DD);
    float rstd = rsqrtf(var + 1e-6f);

    for(int d=threadIdx.x; d<DD; d+=256)
        out[(size_t)row*DD + d] = (srow[d]-mean)*rstd*gamma[d] + beta[d];
}

// ---------------- launch ----------------
extern "C" void kernel_launch(void* const* d_in, const int* in_sizes, int n_in,
                              void* d_out, int out_size)
{
    const float* x      = (const float*)d_in[0];
    const float* vector = (const float*)d_in[1];
    const float* W_val  = (const float*)d_in[4];
    const float* W_op   = (const float*)d_in[5];
    const float* ff1    = (const float*)d_in[6];
    const float* ff1_b  = (const float*)d_in[7];
    const float* ff2    = (const float*)d_in[8];
    const float* ff2_b  = (const float*)d_in[9];
    const float* gamma  = (const float*)d_in[10];
    const float* beta   = (const float*)d_in[11];
    float* out = (float*)d_out;
    (void)in_sizes; (void)n_in; (void)out_size;

    float *csum,*vb,*vbp;
    __half *xh,*cxs,*hh,*Wth,*Wvh,*Woph,*Wct,*Wbt;
    cudaGetSymbolAddress((void**)&xh, g_xh);
    cudaGetSymbolAddress((void**)&cxs, g_cxs);
    cudaGetSymbolAddress((void**)&hh, g_hh);
    cudaGetSymbolAddress((void**)&Wth, g_Wth);
    cudaGetSymbolAddress((void**)&Wvh, g_Wvh);
    cudaGetSymbolAddress((void**)&Woph, g_Woph);
    cudaGetSymbolAddress((void**)&Wct, g_Wct);
    cudaGetSymbolAddress((void**)&Wbt, g_Wbt);
    cudaGetSymbolAddress((void**)&vb, g_vb);
    cudaGetSymbolAddress((void**)&vbp, g_vbp);
    cudaGetSymbolAddress((void**)&csum, g_csum);

    const int gemm_smem = STAGES * STAGE_BYTES;   // 96KB
    cudaFuncSetAttribute(k_gemm<true,false,true,true,false,true>,
                         cudaFuncAttributeMaxDynamicSharedMemorySize, gemm_smem);
    cudaFuncSetAttribute(k_gemm<false,true,false,true,true,true>,
                         cudaFuncAttributeMaxDynamicSharedMemorySize, gemm_smem);
    cudaFuncSetAttribute(k_gemm_s,
                         cudaFuncAttributeMaxDynamicSharedMemorySize, gemm_smem);

    // ---- weight prep ----
    dim3 trb(32,8);
    k_trh2<<<dim3(DD/32, 192), trb>>>(ff1, ff2, Wth);           // ff1_t + ff2_t
    k_xh<<<(MM*DD/4+255)/256, 256>>>(x, xh, MM*DD/4);
    k_xh2<<<dim3((DD*DD/4+255)/256, 2), 256>>>(W_op, Woph, W_val, Wvh, DD*DD/4);
    k_vbp<<<dim3(DD/256, BB, 16), 256>>>(vector, ff1, vbp);
    k_vbr<<<dim3(DD/256, BB), 256>>>(vbp, ff1_b, vb);

    // Wcomb_t[n][o] = sum_j ff1_op[j][n] * W_op[o][j]
    k_gemm_s<<<dim3(16,16),256,gemm_smem>>>(Wth + FF1_T + DD, Woph, Wct, DD, 2*DD, DD);
    // Wbig_t[n][i] = sum_o Wcomb_t[n][o] * W_val[i][o]
    k_gemm_s<<<dim3(16,16),256,gemm_smem>>>(Wct, Wvh, Wbt, DD, DD, DD);

    // ---- cxs = cumsum(x)/(s+1) from fp16 x ----
    k_chunksum<<<256,256>>>(xh, csum);
    k_scan<<<256,256>>>(xh, csum, cxs);

    dim3 gg(DD/128, MM/128);   // (16, 64)

    // h = relu( x@ff1_x + cxs@Wbig + vb )   (fp16 out)
    k_gemm<true,false,true,true,false,true><<<gg,256,gemm_smem>>>(
        xh, cxs, Wth + FF1_T, Wbt, hh,
        nullptr, vb, nullptr, 2*DD, DD, 2*DD);
    // res = relu(h @ ff2 + b) + x   (fp16 residual from xh; fp16 out into cxs — dead now)
    k_gemm<false,true,false,true,true,true><<<gg,256,gemm_smem>>>(
        hh, nullptr, Wth + FF2_T, nullptr, cxs,
        ff2_b, nullptr, xh, DD, DD, DD);
    // out = layernorm(res)
    k_ln<<<MM, 256>>>(cxs, gamma, beta, out);
}